// round 15
// baseline (speedup 1.0000x reference)
#include <cuda_runtime.h>
#include <math.h>

#define D 128
#define MAXN 100000
#define MAXE 1600000
#define BM2 128
#define KC2 32
#define PADS 132   // smem row stride in floats: 528B, multiple of 16B -> LDS.128-safe

// ---------------- scratch (static device globals; 16B-aligned for float4) -----
__device__ __align__(16) float g_agg[(size_t)MAXN * D];  // aggregated MEAN feats
__device__ __align__(16) float g_h[(size_t)MAXN * D];    // pre-BN hidden
__device__ __align__(16) float g_colacc[2 * D];          // col sum | col sumsq
__device__ __align__(16) float g_ab[2 * D];              // bn scale | bn shift
__device__ int g_deg[MAXN];
__device__ int g_off[MAXN + 1];
__device__ int g_cur[MAXN];
__device__ int g_srcidx[MAXE];
__device__ int g_bsum[128];                              // per-block scan sums
__device__ int g_is64;                                   // edge_index dtype flag

// ---------------- f32x2 packed-math helpers (Blackwell FFMA2) -----------------
__device__ __forceinline__ unsigned long long pk2(float lo, float hi) {
    unsigned long long r;
    asm("mov.b64 %0, {%1, %2};" : "=l"(r) : "f"(lo), "f"(hi));
    return r;
}
__device__ __forceinline__ void upk2(unsigned long long v, float& lo, float& hi) {
    asm("mov.b64 {%0, %1}, %2;" : "=f"(lo), "=f"(hi) : "l"(v));
}
__device__ __forceinline__ void fma2(unsigned long long& a, unsigned long long u,
                                     unsigned long long w) {
    asm("fma.rn.f32x2 %0, %1, %2, %0;" : "+l"(a) : "l"(u), "l"(w));
}

// ---------------- 0) zero small scratch ---------------------------------------
__global__ void zero_kernel(int n) {
    int i      = blockIdx.x * blockDim.x + threadIdx.x;
    int stride = gridDim.x * blockDim.x;
    for (int k = i; k < n; k += stride) g_deg[k] = 0;
    if (i < 2 * D) g_colacc[i] = 0.0f;
    if (i == 0) g_is64 = 1;
}

// ---------------- 0b) detect edge_index dtype ---------------------------------
__global__ void detect_kernel(const int* __restrict__ ei32, int n_words32) {
    int limit = min(n_words32, 4096);
    int nz = 0;
    for (int i = threadIdx.x * 2 + 1; i < limit; i += 512)
        nz |= (__ldg(ei32 + i) != 0);
    if (nz) g_is64 = 0;
}

// ---------------- index fetch helper -------------------------------------------
__device__ __forceinline__ int load_idx(const void* ei, int is64, int pos) {
    if (is64) return (int)__ldg((const long long*)ei + pos);
    return __ldg((const int*)ei + pos);
}

// ---------------- 1) count in-degrees (int atomics) ---------------------------
__global__ void count_kernel(const void* __restrict__ ei, int E, int N) {
    int i      = blockIdx.x * blockDim.x + threadIdx.x;
    int stride = gridDim.x * blockDim.x;
    int is64   = g_is64;
    for (int e = i; e < E; e += stride) {
        int d = load_idx(ei, is64, E + e);
        if ((unsigned)d < (unsigned)N) atomicAdd(&g_deg[d], 1);
    }
}

// ---------------- 2) two-level exclusive scan (full-grid) ---------------------
__global__ void scanA_kernel(int n) {
    __shared__ int wsum[32];
    int tid = threadIdx.x, lane = tid & 31, wid = tid >> 5;
    int i = blockIdx.x * 1024 + tid;
    int v = (i < n) ? g_deg[i] : 0;
    int s = v;
#pragma unroll
    for (int o = 1; o < 32; o <<= 1) {
        int t = __shfl_up_sync(0xffffffffu, s, o);
        if (lane >= o) s += t;
    }
    if (lane == 31) wsum[wid] = s;
    __syncthreads();
    if (wid == 0) {
        int ws = wsum[lane];
#pragma unroll
        for (int o = 1; o < 32; o <<= 1) {
            int t = __shfl_up_sync(0xffffffffu, ws, o);
            if (lane >= o) ws += t;
        }
        wsum[lane] = ws;
    }
    __syncthreads();
    int incl = s + (wid > 0 ? wsum[wid - 1] : 0);
    if (i < n) g_off[i] = incl - v;
    if (tid == 1023) g_bsum[blockIdx.x] = incl;
}

__global__ void scanB_kernel(int nb, int n) {
    __shared__ int wsum[4];
    int tid = threadIdx.x, lane = tid & 31, wid = tid >> 5;
    int v = (tid < nb) ? g_bsum[tid] : 0;
    int s = v;
#pragma unroll
    for (int o = 1; o < 32; o <<= 1) {
        int t = __shfl_up_sync(0xffffffffu, s, o);
        if (lane >= o) s += t;
    }
    if (lane == 31) wsum[wid] = s;
    __syncthreads();
    int base = 0;
    for (int w = 0; w < wid; w++) base += wsum[w];
    int incl = s + base;
    if (tid < nb) g_bsum[tid] = incl - v;
    if (tid == 127) g_off[n] = incl;
}

__global__ void scanC_kernel(int n) {
    int i = blockIdx.x * 1024 + threadIdx.x;
    if (i < n) {
        int o = g_off[i] + g_bsum[blockIdx.x];
        g_off[i] = o;
        g_cur[i] = o;
    }
}

// ---------------- 3) fill CSR buckets (int atomics on cursors) ----------------
__global__ void fill_kernel(const void* __restrict__ ei, int E, int N) {
    int i      = blockIdx.x * blockDim.x + threadIdx.x;
    int stride = gridDim.x * blockDim.x;
    int is64   = g_is64;
    for (int e = i; e < E; e += stride) {
        int s = load_idx(ei, is64, e);
        int d = load_idx(ei, is64, E + e);
        if ((unsigned)d < (unsigned)N) {
            int pos = atomicAdd(&g_cur[d], 1);
            if ((unsigned)s >= (unsigned)N) s = 0;   // safety, never expected
            g_srcidx[pos] = s;
        }
    }
}

// ---------------- 4) gather + mean: one warp per node, zero atomics -----------
__global__ void gather_kernel(const float* __restrict__ x, int N) {
    int gw   = (blockIdx.x * blockDim.x + threadIdx.x) >> 5;
    int lane = threadIdx.x & 31;
    int nw   = (gridDim.x * blockDim.x) >> 5;
    for (int v = gw; v < N; v += nw) {
        int beg = g_off[v], end = g_off[v + 1];
        float4 acc = make_float4(0.f, 0.f, 0.f, 0.f);
        for (int j = beg; j < end; j += 32) {
            int idx = (j + lane < end) ? __ldg(g_srcidx + j + lane) : 0;
            int m = min(32, end - j);
            for (int t = 0; t < m; t++) {
                int s = __shfl_sync(0xffffffffu, idx, t);
                float4 xv = __ldg((const float4*)(x + (size_t)s * D) + lane);
                acc.x += xv.x; acc.y += xv.y; acc.z += xv.z; acc.w += xv.w;
            }
        }
        float inv = 1.0f / fmaxf((float)(end - beg), 1.0f);
        acc.x *= inv; acc.y *= inv; acc.z *= inv; acc.w *= inv;
        ((float4*)(g_agg + (size_t)v * D))[lane] = acc;
    }
}

// ---------------- 5) fused GEMM: h = [agg | x] @ [Wl | Wr]^T + b --------------
// BM=128 rows, 256 threads, thread tile 8x8, k-major smem with stride PADS=132
// (528B rows: every float4 read 16B-aligned; w compute read = 2-phase minimum).
// Per k-step per thread: 4x LDS.128 = 64B for 128 FLOP (0.5 B/FLOP).
// Col-pair f32x2: acc += (u,u)*(w_j,w_j+1), w-pair direct from LDS.128 regs.
__global__ void __launch_bounds__(256, 2) gemm_kernel(
    const float* __restrict__ x,  const float* __restrict__ Wl,
    const float* __restrict__ bl, const float* __restrict__ Wr, int N)
{
    __shared__ __align__(16) float u_s[KC2][PADS];   // [k][row]
    __shared__ __align__(16) float w_s[KC2][PADS];   // [k][j]
    __shared__ float scol[2 * D];                    // sum | sumsq

    int tid  = threadIdx.x;
    int row0 = blockIdx.x * BM2;
    int ct   = tid & 15;    // col group: cols 4*(ct+16g), g=0..1
    int rt   = tid >> 4;    // row group: rows 8*rt .. 8*rt+7

    if (tid < 2 * D) scol[tid] = 0.0f;

    unsigned long long acc[8][4];   // [row i][colpair]: pairs (j,j+1)
#pragma unroll
    for (int i = 0; i < 8; i++)
#pragma unroll
        for (int c = 0; c < 4; c++) acc[i][c] = 0ull;

    for (int kc = 0; kc < 256 / KC2; kc++) {
        int k0 = kc * KC2;
        const float* Wsrc = (k0 < 128) ? Wl : Wr;
        const float* Usrc = (k0 < 128) ? g_agg : x;
        int kk = (k0 < 128) ? k0 : (k0 - 128);

        __syncthreads();   // previous chunk fully consumed
        // W chunk: 128 j x 32 k, float4 over k, transposed store
        for (int idx = tid; idx < 128 * (KC2 / 4); idx += 256) {
            int j = idx >> 3, kq = idx & 7;
            float4 v = __ldg((const float4*)(Wsrc + j * D + kk) + kq);
            w_s[kq * 4 + 0][j] = v.x;
            w_s[kq * 4 + 1][j] = v.y;
            w_s[kq * 4 + 2][j] = v.z;
            w_s[kq * 4 + 3][j] = v.w;
        }
        // U chunk: 128 rows x 32 k, float4 over k, transposed store
        for (int idx = tid; idx < BM2 * (KC2 / 4); idx += 256) {
            int row = idx >> 3, kq = idx & 7;
            int gr = row0 + row;
            float4 v = make_float4(0.f, 0.f, 0.f, 0.f);
            if (gr < N) v = __ldg((const float4*)(Usrc + (size_t)gr * D + kk) + kq);
            u_s[kq * 4 + 0][row] = v.x;
            u_s[kq * 4 + 1][row] = v.y;
            u_s[kq * 4 + 2][row] = v.z;
            u_s[kq * 4 + 3][row] = v.w;
        }
        __syncthreads();

#pragma unroll
        for (int k = 0; k < KC2; k++) {
            float4 ua = *(const float4*)&u_s[k][rt * 8];
            float4 ub = *(const float4*)&u_s[k][rt * 8 + 4];
            unsigned long long u2[8];
            u2[0] = pk2(ua.x, ua.x); u2[1] = pk2(ua.y, ua.y);
            u2[2] = pk2(ua.z, ua.z); u2[3] = pk2(ua.w, ua.w);
            u2[4] = pk2(ub.x, ub.x); u2[5] = pk2(ub.y, ub.y);
            u2[6] = pk2(ub.z, ub.z); u2[7] = pk2(ub.w, ub.w);
#pragma unroll
            for (int g = 0; g < 2; g++) {
                float4 w4 = *(const float4*)&w_s[k][4 * (ct + 16 * g)];
                unsigned long long w01 = ((const unsigned long long*)&w4)[0];
                unsigned long long w23 = ((const unsigned long long*)&w4)[1];
#pragma unroll
                for (int i = 0; i < 8; i++) {
                    fma2(acc[i][2 * g],     u2[i], w01);
                    fma2(acc[i][2 * g + 1], u2[i], w23);
                }
            }
        }
    }

    // epilogue: + bias, store h (float2), per-column BN partials
#pragma unroll
    for (int g = 0; g < 2; g++)
#pragma unroll
    for (int hh = 0; hh < 2; hh++) {
        int j = 4 * (ct + 16 * g) + 2 * hh;
        float b0 = __ldg(bl + j), b1 = __ldg(bl + j + 1);
        float s0 = 0.f, sq0 = 0.f, s1 = 0.f, sq1 = 0.f;
#pragma unroll
        for (int i = 0; i < 8; i++) {
            int row = row0 + rt * 8 + i;
            float v0, v1;
            upk2(acc[i][2 * g + hh], v0, v1);
            v0 += b0; v1 += b1;
            if (row < N) {
                float2 st; st.x = v0; st.y = v1;
                *(float2*)&g_h[(size_t)row * D + j] = st;
                s0 += v0; sq0 += v0 * v0;
                s1 += v1; sq1 += v1 * v1;
            }
        }
        atomicAdd(&scol[j],         s0);
        atomicAdd(&scol[D + j],     sq0);
        atomicAdd(&scol[j + 1],     s1);
        atomicAdd(&scol[D + j + 1], sq1);
    }
    __syncthreads();
    if (tid < 2 * D) atomicAdd(&g_colacc[tid], scol[tid]);
}

// ---------------- 6) BN parameter finalize (1 block, 128 threads) -------------
__global__ void bnfin_kernel(const float* __restrict__ gamma,
                             const float* __restrict__ beta, float invN) {
    int j = threadIdx.x;
    float mu  = g_colacc[j] * invN;
    float var = g_colacc[D + j] * invN - mu * mu;
    float rs  = rsqrtf(var + 1e-5f);
    float a   = gamma[j] * rs;
    g_ab[j]     = a;
    g_ab[D + j] = beta[j] - mu * a;
}

// ---------------- 7) out = relu(h*a + b + x), float4 vectorized ---------------
__global__ void finalize_kernel(const float* __restrict__ x,
                                float* __restrict__ out, int N) {
    int idx   = blockIdx.x * blockDim.x + threadIdx.x;
    int total = N * (D / 4);
    if (idx >= total) return;
    int c4 = idx & 31;
    float4 h  = ((const float4*)g_h)[idx];
    float4 xv = __ldg((const float4*)x + idx);
    const float4* a4 = (const float4*)g_ab;
    float4 a = a4[c4];
    float4 b = a4[32 + c4];
    float4 o;
    o.x = fmaxf(fmaf(h.x, a.x, b.x) + xv.x, 0.0f);
    o.y = fmaxf(fmaf(h.y, a.y, b.y) + xv.y, 0.0f);
    o.z = fmaxf(fmaf(h.z, a.z, b.z) + xv.z, 0.0f);
    o.w = fmaxf(fmaf(h.w, a.w, b.w) + xv.w, 0.0f);
    ((float4*)out)[idx] = o;
}

// ------------------------------------------------------------------------------
extern "C" void kernel_launch(void* const* d_in, const int* in_sizes, int n_in,
                              void* d_out, int out_size) {
    const float* x     = (const float*)d_in[0];
    const void*  ei    = d_in[1];                 // int32 OR int64, detected on device
    const float* Wl    = (const float*)d_in[2];
    const float* bl    = (const float*)d_in[3];
    const float* Wr    = (const float*)d_in[4];
    const float* gamma = (const float*)d_in[5];
    const float* beta  = (const float*)d_in[6];
    int N = in_sizes[0] / D;
    int E = in_sizes[1] / 2;

    zero_kernel<<<148, 256>>>(N);
    detect_kernel<<<1, 256>>>((const int*)ei, 2 * E);
    count_kernel<<<1184, 256>>>(ei, E, N);

    int nb = (N + 1023) / 1024;   // <=128 for MAXN=100000
    scanA_kernel<<<nb, 1024>>>(N);
    scanB_kernel<<<1, 128>>>(nb, N);
    scanC_kernel<<<nb, 1024>>>(N);

    fill_kernel<<<1184, 256>>>(ei, E, N);
    gather_kernel<<<1184, 256>>>(x, N);

    gemm_kernel<<<(N + BM2 - 1) / BM2, 256>>>(x, Wl, bl, Wr, N);

    bnfin_kernel<<<1, 128>>>(gamma, beta, 1.0f / (float)N);

    int total4 = N * (D / 4);
    finalize_kernel<<<(total4 + 255) / 256, 256>>>(x, (float*)d_out, N);
}

// round 17
// speedup vs baseline: 1.0660x; 1.0660x over previous
#include <cuda_runtime.h>
#include <math.h>

#define D 128
#define MAXN 100000
#define MAXE 1600000
#define BM 64
#define KC 32

// ---------------- scratch (static device globals; 16B-aligned for float4) -----
__device__ __align__(16) float g_agg[(size_t)MAXN * D];  // aggregated MEAN feats
__device__ __align__(16) float g_h[(size_t)MAXN * D];    // pre-BN hidden
__device__ __align__(16) float g_colacc[2 * D];          // col sum | col sumsq
__device__ int g_deg[MAXN];
__device__ int g_off[MAXN + 1];
__device__ int g_cur[MAXN];
__device__ int g_srcidx[MAXE];
__device__ volatile int g_scanst[128];                   // block status (0/1)
__device__ int g_scanval[128];                           // block aggregates
__device__ int g_is64;                                   // edge_index dtype flag

// ---------------- f32x2 packed-math helpers (Blackwell FFMA2) -----------------
__device__ __forceinline__ unsigned long long pk2(float lo, float hi) {
    unsigned long long r;
    asm("mov.b64 %0, {%1, %2};" : "=l"(r) : "f"(lo), "f"(hi));
    return r;
}
__device__ __forceinline__ void upk2(unsigned long long v, float& lo, float& hi) {
    asm("mov.b64 {%0, %1}, %2;" : "=f"(lo), "=f"(hi) : "l"(v));
}
__device__ __forceinline__ void fma2(unsigned long long& a, unsigned long long u,
                                     unsigned long long w) {
    asm("fma.rn.f32x2 %0, %1, %2, %0;" : "+l"(a) : "l"(u), "l"(w));
}

// ---------------- 0) zero scratch + detect edge dtype (one kernel) ------------
// int64 nonneg values < 2^31 have zero high words at every odd 32-bit position;
// int32 node indices there are ~never all zero over 4096 probed words.
__global__ void zero_kernel(const int* __restrict__ ei32, int n_words32, int n) {
    int i      = blockIdx.x * blockDim.x + threadIdx.x;
    int stride = gridDim.x * blockDim.x;
    for (int k = i; k < n; k += stride) g_deg[k] = 0;
    if (i < 2 * D) g_colacc[i] = 0.0f;
    if (i < 128) g_scanst[i] = 0;
    if (i == 0) g_is64 = 1;
    if (blockIdx.x == 0) {
        int limit = min(n_words32, 4096);
        int nz = 0;
        for (int k = threadIdx.x * 2 + 1; k < limit; k += 512)
            nz |= (__ldg(ei32 + k) != 0);
        if (nz) g_is64 = 0;
    }
}

// ---------------- index fetch helper -------------------------------------------
__device__ __forceinline__ int load_idx(const void* ei, int is64, int pos) {
    if (is64) return (int)__ldg((const long long*)ei + pos);
    return __ldg((const int*)ei + pos);
}

// ---------------- 1) count in-degrees (int atomics) ---------------------------
__global__ void count_kernel(const void* __restrict__ ei, int E, int N) {
    int i      = blockIdx.x * blockDim.x + threadIdx.x;
    int stride = gridDim.x * blockDim.x;
    int is64   = g_is64;
    for (int e = i; e < E; e += stride) {
        int d = load_idx(ei, is64, E + e);
        if ((unsigned)d < (unsigned)N) atomicAdd(&g_deg[d], 1);
    }
}

// ---------------- 2) single-pass exclusive scan --------------------------------
// nb <= 128 blocks, ALL resident simultaneously (nb < #SMs) -> spin-wait safe.
// Each block: local scan, publish aggregate, warp 0 sums predecessors'
// aggregates (spinning until published), add base, write off/cur.
__global__ void scan_kernel(int n, int nb) {
    __shared__ int wsum[32];
    __shared__ int s_base;
    int tid = threadIdx.x, lane = tid & 31, wid = tid >> 5;
    int b = blockIdx.x;
    int i = b * 1024 + tid;
    int v = (i < n) ? g_deg[i] : 0;
    int s = v;
#pragma unroll
    for (int o = 1; o < 32; o <<= 1) {
        int t = __shfl_up_sync(0xffffffffu, s, o);
        if (lane >= o) s += t;
    }
    if (lane == 31) wsum[wid] = s;
    __syncthreads();
    if (wid == 0) {
        int ws = wsum[lane];
#pragma unroll
        for (int o = 1; o < 32; o <<= 1) {
            int t = __shfl_up_sync(0xffffffffu, ws, o);
            if (lane >= o) ws += t;
        }
        wsum[lane] = ws;
    }
    __syncthreads();
    int incl = s + (wid > 0 ? wsum[wid - 1] : 0);
    int total = wsum[31];

    // publish this block's aggregate
    if (tid == 0) {
        g_scanval[b] = total;
        __threadfence();
        g_scanst[b] = 1;
    }
    // warp 0 sums predecessor aggregates
    if (wid == 0) {
        int base = 0;
        for (int j = lane; j < b; j += 32) {
            while (g_scanst[j] == 0) { }
            base += g_scanval[j];
        }
#pragma unroll
        for (int o = 16; o > 0; o >>= 1)
            base += __shfl_down_sync(0xffffffffu, base, o);
        if (lane == 0) s_base = base;
    }
    __syncthreads();
    __threadfence_block();
    int base = s_base;
    int excl = base + incl - v;
    if (i < n) { g_off[i] = excl; g_cur[i] = excl; }
    if (b == nb - 1 && tid == 1023) g_off[n] = base + incl;
}

// ---------------- 3) fill CSR buckets (int atomics on cursors) ----------------
__global__ void fill_kernel(const void* __restrict__ ei, int E, int N) {
    int i      = blockIdx.x * blockDim.x + threadIdx.x;
    int stride = gridDim.x * blockDim.x;
    int is64   = g_is64;
    for (int e = i; e < E; e += stride) {
        int s = load_idx(ei, is64, e);
        int d = load_idx(ei, is64, E + e);
        if ((unsigned)d < (unsigned)N) {
            int pos = atomicAdd(&g_cur[d], 1);
            if ((unsigned)s >= (unsigned)N) s = 0;   // safety, never expected
            g_srcidx[pos] = s;
        }
    }
}

// ---------------- 4) gather + mean: one warp per node, MLP=4 -------------------
__global__ void gather_kernel(const float* __restrict__ x, int N) {
    int gw   = (blockIdx.x * blockDim.x + threadIdx.x) >> 5;
    int lane = threadIdx.x & 31;
    int nw   = (gridDim.x * blockDim.x) >> 5;
    for (int v = gw; v < N; v += nw) {
        int beg = g_off[v], end = g_off[v + 1];
        float4 a0 = make_float4(0.f, 0.f, 0.f, 0.f);
        float4 a1 = a0, a2 = a0, a3 = a0;
        for (int j = beg; j < end; j += 32) {
            int idx = (j + lane < end) ? __ldg(g_srcidx + j + lane) : 0;
            int m = min(32, end - j);
            int t = 0;
            for (; t + 4 <= m; t += 4) {
                int s0 = __shfl_sync(0xffffffffu, idx, t);
                int s1 = __shfl_sync(0xffffffffu, idx, t + 1);
                int s2 = __shfl_sync(0xffffffffu, idx, t + 2);
                int s3 = __shfl_sync(0xffffffffu, idx, t + 3);
                float4 v0 = __ldg((const float4*)(x + (size_t)s0 * D) + lane);
                float4 v1 = __ldg((const float4*)(x + (size_t)s1 * D) + lane);
                float4 v2 = __ldg((const float4*)(x + (size_t)s2 * D) + lane);
                float4 v3 = __ldg((const float4*)(x + (size_t)s3 * D) + lane);
                a0.x += v0.x; a0.y += v0.y; a0.z += v0.z; a0.w += v0.w;
                a1.x += v1.x; a1.y += v1.y; a1.z += v1.z; a1.w += v1.w;
                a2.x += v2.x; a2.y += v2.y; a2.z += v2.z; a2.w += v2.w;
                a3.x += v3.x; a3.y += v3.y; a3.z += v3.z; a3.w += v3.w;
            }
            for (; t < m; t++) {
                int s0 = __shfl_sync(0xffffffffu, idx, t);
                float4 v0 = __ldg((const float4*)(x + (size_t)s0 * D) + lane);
                a0.x += v0.x; a0.y += v0.y; a0.z += v0.z; a0.w += v0.w;
            }
        }
        float4 acc;
        acc.x = (a0.x + a1.x) + (a2.x + a3.x);
        acc.y = (a0.y + a1.y) + (a2.y + a3.y);
        acc.z = (a0.z + a1.z) + (a2.z + a3.z);
        acc.w = (a0.w + a1.w) + (a2.w + a3.w);
        float inv = 1.0f / fmaxf((float)(end - beg), 1.0f);
        acc.x *= inv; acc.y *= inv; acc.z *= inv; acc.w *= inv;
        ((float4*)(g_agg + (size_t)v * D))[lane] = acc;
    }
}

// ---------------- 5) fused GEMM (r13 version, best known) ---------------------
// BM=64 rows x 128 cols per block, 256 threads, K=256 in 8 chunks of 32.
// Thread (jt=tid&15, rt=tid>>4) owns 4 rows x 8 cols via packed fma.rn.f32x2
// (row-pairs share the broadcast W operand). BN column stats fused.
__global__ void __launch_bounds__(256) gemm_kernel(
    const float* __restrict__ x,  const float* __restrict__ Wl,
    const float* __restrict__ bl, const float* __restrict__ Wr, int N)
{
    __shared__ __align__(16) float u_s[KC][68];   // [k][row]
    __shared__ float w_s[128][33];                // [j][k]
    __shared__ float scol[2 * D];                 // sum | sumsq

    int tid  = threadIdx.x;
    int row0 = blockIdx.x * BM;
    int jt   = tid & 15;    // column group: cols jt + 16*c
    int rt   = tid >> 4;    // row group:    rows 4*rt .. 4*rt+3

    if (tid < 2 * D) scol[tid] = 0.0f;

    unsigned long long acc2[2][8];   // [row-pair][col]; pair0=rows(0,1), pair1=(2,3)
#pragma unroll
    for (int p = 0; p < 2; p++)
#pragma unroll
        for (int c = 0; c < 8; c++) acc2[p][c] = 0ull;

    for (int kc = 0; kc < 256 / KC; kc++) {
        int k0 = kc * KC;
        const float* Wsrc = (k0 < 128) ? Wl : Wr;
        const float* Usrc = (k0 < 128) ? g_agg : x;
        int kk = (k0 < 128) ? k0 : (k0 - 128);

        __syncthreads();   // previous chunk fully consumed
        for (int idx = tid; idx < 128 * KC; idx += 256) {
            int j = idx >> 5, k = idx & 31;
            w_s[j][k] = __ldg(Wsrc + j * D + kk + k);
        }
        for (int idx = tid; idx < BM * KC; idx += 256) {
            int row = idx >> 5, k = idx & 31;
            int gr = row0 + row;
            float v = (gr < N) ? __ldg(Usrc + (size_t)gr * D + kk + k) : 0.0f;
            u_s[k][row] = v;
        }
        __syncthreads();

#pragma unroll
        for (int k = 0; k < KC; k++) {
            float4 u4 = *(const float4*)&u_s[k][rt * 4];
            unsigned long long ua = pk2(u4.x, u4.y);
            unsigned long long ub = pk2(u4.z, u4.w);
#pragma unroll
            for (int c = 0; c < 8; c++) {
                float w = w_s[jt + 16 * c][k];
                unsigned long long w2 = pk2(w, w);
                fma2(acc2[0][c], ua, w2);
                fma2(acc2[1][c], ub, w2);
            }
        }
    }

    // epilogue: + bias, store h, per-column BN partials
#pragma unroll
    for (int c = 0; c < 8; c++) {
        int j = jt + 16 * c;
        float bj = __ldg(bl + j);
        float s = 0.0f, sq = 0.0f;
        float v[4];
        upk2(acc2[0][c], v[0], v[1]);
        upk2(acc2[1][c], v[2], v[3]);
#pragma unroll
        for (int i = 0; i < 4; i++) {
            int row = row0 + rt * 4 + i;
            if (row < N) {
                float h = v[i] + bj;
                g_h[(size_t)row * D + j] = h;
                s += h; sq += h * h;
            }
        }
        atomicAdd(&scol[j], s);
        atomicAdd(&scol[D + j], sq);
    }
    __syncthreads();
    if (tid < 2 * D) atomicAdd(&g_colacc[tid], scol[tid]);
}

// ---------------- 6) finalize: BN coefficients + relu(h*a + b + x) -------------
// Each block recomputes the 128 BN coefficients from g_colacc (cheap), then
// grid-strides over the output. bnfin kernel eliminated.
__global__ void finalize_kernel(const float* __restrict__ x,
                                const float* __restrict__ gamma,
                                const float* __restrict__ beta,
                                float* __restrict__ out, int N, float invN) {
    __shared__ __align__(16) float a_s[D], b_s[D];
    int tid = threadIdx.x;
    if (tid < D) {
        float mu  = g_colacc[tid] * invN;
        float var = g_colacc[D + tid] * invN - mu * mu;
        float rs  = rsqrtf(var + 1e-5f);
        float a   = __ldg(gamma + tid) * rs;
        a_s[tid] = a;
        b_s[tid] = __ldg(beta + tid) - mu * a;
    }
    __syncthreads();

    int idx    = blockIdx.x * blockDim.x + tid;
    int stride = gridDim.x * blockDim.x;
    int total  = N * (D / 4);
    const float4* a4 = (const float4*)a_s;
    const float4* b4 = (const float4*)b_s;
    for (; idx < total; idx += stride) {
        int c4 = idx & 31;
        float4 h  = ((const float4*)g_h)[idx];
        float4 xv = __ldg((const float4*)x + idx);
        float4 a = a4[c4];
        float4 b = b4[c4];
        float4 o;
        o.x = fmaxf(fmaf(h.x, a.x, b.x) + xv.x, 0.0f);
        o.y = fmaxf(fmaf(h.y, a.y, b.y) + xv.y, 0.0f);
        o.z = fmaxf(fmaf(h.z, a.z, b.z) + xv.z, 0.0f);
        o.w = fmaxf(fmaf(h.w, a.w, b.w) + xv.w, 0.0f);
        ((float4*)out)[idx] = o;
    }
}

// ------------------------------------------------------------------------------
extern "C" void kernel_launch(void* const* d_in, const int* in_sizes, int n_in,
                              void* d_out, int out_size) {
    const float* x     = (const float*)d_in[0];
    const void*  ei    = d_in[1];                 // int32 OR int64, detected on device
    const float* Wl    = (const float*)d_in[2];
    const float* bl    = (const float*)d_in[3];
    const float* Wr    = (const float*)d_in[4];
    const float* gamma = (const float*)d_in[5];
    const float* beta  = (const float*)d_in[6];
    int N = in_sizes[0] / D;
    int E = in_sizes[1] / 2;

    zero_kernel<<<148, 256>>>((const int*)ei, 2 * E, N);
    count_kernel<<<1184, 256>>>(ei, E, N);

    int nb = (N + 1023) / 1024;   // <=128; all blocks resident (nb < #SMs req.)
    scan_kernel<<<nb, 1024>>>(N, nb);

    fill_kernel<<<1184, 256>>>(ei, E, N);
    gather_kernel<<<1184, 256>>>(x, N);

    gemm_kernel<<<(N + BM - 1) / BM, 256>>>(x, Wl, bl, Wr, N);

    finalize_kernel<<<1184, 256>>>(x, gamma, beta, (float*)d_out, N,
                                   1.0f / (float)N);
}